// round 1
// baseline (speedup 1.0000x reference)
#include <cuda_runtime.h>
#include <math.h>

#define Bn 8
#define Sn 2048
#define Dn 128
#define Ln 3
#define BS (Bn*Sn)          // 16384 rows
#define CHK 64
#define NCH (Sn/CHK)        // 32 chunks per batch
#define SCALEF 0.08838834764831845f   // 128^-0.5

// ---------------- static device scratch (no allocations allowed) ----------------
__device__ float g_G[Ln*Dn*Dn];      // Wq @ Wk^T per layer
__device__ float g_u[Ln*Dn];         // Wq @ bk
__device__ float g_v[Ln*Dn];         // Wk @ bq
__device__ float g_beta[Ln];         // bq . bk
__device__ float g_HG[Ln*BS*Dn];     // H @ G per layer (25 MB)
__device__ float g_theta[Ln*BS];
__device__ float g_phi[Ln*BS];
__device__ float g_a[Ln*BS];         // H . u
__device__ float g_c[Ln*BS];         // H . v
__device__ float g_Z[BS];
__device__ float g_LDJ[BS];
__device__ float g_U[Bn*NCH*Dn];     // per-chunk sum of H_t * Z_t
__device__ float g_Cex[Bn*NCH*Dn];   // exclusive prefix of g_U
__device__ float g_sig[Bn*NCH];      // per-chunk sum of Z_t
__device__ float g_gam[Bn*NCH];      // per-chunk sum of c_t * Z_t
__device__ float g_sigex[Bn*NCH];
__device__ float g_gamex[Bn*NCH];

// ---------------- P0: G = Wq Wk^T, u, v, beta ----------------
__global__ void prep_G(const float* __restrict__ Wq, const float* __restrict__ Wk,
                       const float* __restrict__ bq, const float* __restrict__ bk) {
    int l = blockIdx.x;
    int drow = blockIdx.y;
    int e = threadIdx.x;            // 128 threads
    __shared__ float wq[Dn];
    wq[e] = Wq[l*Dn*Dn + drow*Dn + e];
    __syncthreads();
    const float* wkrow = Wk + l*Dn*Dn + e*Dn;
    float acc = 0.f;
    #pragma unroll 8
    for (int j = 0; j < Dn; j++) acc += wq[j] * wkrow[j];
    g_G[l*Dn*Dn + drow*Dn + e] = acc;
    if (e == 0) {
        float s = 0.f;
        const float* bkl = bk + l*Dn;
        for (int j = 0; j < Dn; j++) s += wq[j] * bkl[j];
        g_u[l*Dn + drow] = s;
    }
    if (drow == 0) {
        float s = 0.f;
        const float* bql = bq + l*Dn;
        for (int j = 0; j < Dn; j++) s += wkrow[j] * bql[j];
        g_v[l*Dn + e] = s;
        if (e == 0) {
            float sb = 0.f;
            for (int j = 0; j < Dn; j++) sb += bql[j] * bk[l*Dn + j];
            g_beta[l] = sb;
        }
    }
}

// ---------------- P1: per-row MVs (EL0, a, c) + Z/LDJ init ----------------
__global__ void prep_rows(const float* __restrict__ H, const float* __restrict__ Y,
                          const float* __restrict__ MQ, const float* __restrict__ wi,
                          const float* __restrict__ bi) {
    __shared__ float sw[7*Dn];   // wi | u0 u1 u2 | v0 v1 v2
    int tid = threadIdx.x;       // 256
    for (int i = tid; i < 7*Dn; i += 256) {
        if (i < Dn)            sw[i] = wi[i];
        else if (i < 4*Dn)     sw[i] = g_u[i - Dn];
        else                   sw[i] = g_v[i - 4*Dn];
    }
    __syncthreads();
    int warp = tid >> 5, lane = tid & 31;
    int row = blockIdx.x * 8 + warp;
    const float4* h4 = (const float4*)(H + row*Dn);
    float4 hv = h4[lane];
    float p[7];
    #pragma unroll
    for (int k = 0; k < 7; k++) {
        const float4* w4 = (const float4*)(sw + k*Dn);
        float4 wv = w4[lane];
        p[k] = hv.x*wv.x + hv.y*wv.y + hv.z*wv.z + hv.w*wv.w;
    }
    #pragma unroll
    for (int off = 16; off > 0; off >>= 1) {
        #pragma unroll
        for (int k = 0; k < 7; k++) p[k] += __shfl_down_sync(0xffffffffu, p[k], off);
    }
    if (lane == 0) {
        float el0 = p[0] + bi[0];
        float y = Y[row], mq = MQ[row];
        g_Z[row]   = (y*mq - el0) * mq;
        g_LDJ[row] = 1.0f;
        #pragma unroll
        for (int l = 0; l < Ln; l++) {
            g_a[l*BS + row] = p[1 + l];
            g_c[l*BS + row] = p[4 + l];
        }
    }
}

// ---------------- P2: fused projection GEMM ----------------
// grid.y = 9: w = l*3 + kind; kind 0: HG = H@G (write tile)
//                             kind 1: theta = exp(tanh(relu(H@tW1+tb1)@tW2+tb2))
//                             kind 2: phi   = relu(H@pW1+pb1)@pW2+pb2
__global__ void __launch_bounds__(256) gemm_proj(
    const float* __restrict__ H,
    const float* __restrict__ tW1, const float* __restrict__ tb1,
    const float* __restrict__ tW2, const float* __restrict__ tb2,
    const float* __restrict__ pW1, const float* __restrict__ pb1,
    const float* __restrict__ pW2, const float* __restrict__ pb2) {

    int w = blockIdx.y;
    int l = w / 3, kind = w - l*3;
    const float* Wmat;
    const float* b1 = nullptr;
    if (kind == 0)      { Wmat = g_G + l*Dn*Dn; }
    else if (kind == 1) { Wmat = tW1 + l*Dn*Dn; b1 = tb1 + l*Dn; }
    else                { Wmat = pW1 + l*Dn*Dn; b1 = pb1 + l*Dn; }

    int m0 = blockIdx.x * 64;
    __shared__ float As[16][64];
    __shared__ float Bs[16][128];
    int tid = threadIdx.x;
    int tx = tid & 31, ty = tid >> 5;   // tx: 4 cols (n=tx*4), ty: 8 rows (m=ty*8+i)
    float acc[8][4];
    #pragma unroll
    for (int i = 0; i < 8; i++)
        #pragma unroll
        for (int j = 0; j < 4; j++) acc[i][j] = 0.f;

    int r = tid >> 2, kq = tid & 3;
    for (int k0 = 0; k0 < Dn; k0 += 16) {
        float4 av = *(const float4*)(H + (m0 + r)*Dn + k0 + kq*4);
        As[kq*4+0][r] = av.x; As[kq*4+1][r] = av.y;
        As[kq*4+2][r] = av.z; As[kq*4+3][r] = av.w;
        #pragma unroll
        for (int it = 0; it < 2; it++) {
            int idx = tid + it*256;
            int kk = idx >> 5, nn = (idx & 31) * 4;
            *(float4*)&Bs[kk][nn] = *(const float4*)(Wmat + (k0 + kk)*Dn + nn);
        }
        __syncthreads();
        #pragma unroll
        for (int k = 0; k < 16; k++) {
            float4 b  = *(float4*)&Bs[k][tx*4];
            float4 a0 = *(float4*)&As[k][ty*8];
            float4 a1 = *(float4*)&As[k][ty*8 + 4];
            float am[8] = {a0.x, a0.y, a0.z, a0.w, a1.x, a1.y, a1.z, a1.w};
            #pragma unroll
            for (int i = 0; i < 8; i++) {
                acc[i][0] += am[i]*b.x; acc[i][1] += am[i]*b.y;
                acc[i][2] += am[i]*b.z; acc[i][3] += am[i]*b.w;
            }
        }
        __syncthreads();
    }

    if (kind == 0) {
        float* out = g_HG + l*BS*Dn;
        #pragma unroll
        for (int i = 0; i < 8; i++) {
            int m = m0 + ty*8 + i;
            *(float4*)(out + m*Dn + tx*4) =
                make_float4(acc[i][0], acc[i][1], acc[i][2], acc[i][3]);
        }
    } else {
        const float* W2 = (kind == 1 ? tW2 : pW2) + l*Dn;
        float b2 = (kind == 1 ? tb2 : pb2)[l];
        float4 bb  = *(const float4*)(b1 + tx*4);
        float4 w2v = *(const float4*)(W2 + tx*4);
        float* out = (kind == 1 ? g_theta : g_phi) + l*BS;
        #pragma unroll
        for (int i = 0; i < 8; i++) {
            float h0 = fmaxf(acc[i][0] + bb.x, 0.f);
            float h1 = fmaxf(acc[i][1] + bb.y, 0.f);
            float h2 = fmaxf(acc[i][2] + bb.z, 0.f);
            float h3 = fmaxf(acc[i][3] + bb.w, 0.f);
            float part = h0*w2v.x + h1*w2v.y + h2*w2v.z + h3*w2v.w;
            #pragma unroll
            for (int off = 16; off > 0; off >>= 1)
                part += __shfl_down_sync(0xffffffffu, part, off);
            if (tx == 0) {
                float val = part + b2;
                int m = m0 + ty*8 + i;
                out[m] = (kind == 1) ? expf(tanhf(val)) : val;
            }
        }
    }
}

// ---------------- K1: per-chunk sums U = sum H_t Z_t, sigma, gamma ----------------
__global__ void chunk_sums(const float* __restrict__ H, int l) {
    int blk = blockIdx.x;                 // Bn*NCH
    int b = blk / NCH, ch = blk % NCH;
    int base = b*Sn + ch*CHK;
    __shared__ float zs[CHK], cs[CHK];
    int tid = threadIdx.x;                // 128
    if (tid < CHK) {
        zs[tid] = g_Z[base + tid];
        cs[tid] = g_c[l*BS + base + tid];
    }
    __syncthreads();
    float acc = 0.f;
    const float* Hp = H + base*Dn + tid;
    #pragma unroll 8
    for (int t = 0; t < CHK; t++) acc += Hp[t*Dn] * zs[t];
    g_U[blk*Dn + tid] = acc;
    if (tid == 0) {
        float s = 0.f, g = 0.f;
        for (int t = 0; t < CHK; t++) { s += zs[t]; g += cs[t]*zs[t]; }
        g_sig[blk] = s; g_gam[blk] = g;
    }
}

// ---------------- K2: exclusive chunk prefix ----------------
__global__ void chunk_prefix() {
    int b = blockIdx.x;      // Bn
    int tid = threadIdx.x;   // 128
    float acc = 0.f;
    for (int ch = 0; ch < NCH; ch++) {
        int idx = (b*NCH + ch)*Dn + tid;
        g_Cex[idx] = acc;
        acc += g_U[idx];
    }
    if (tid == 0) {
        float s = 0.f, g = 0.f;
        for (int ch = 0; ch < NCH; ch++) {
            int i = b*NCH + ch;
            g_sigex[i] = s; s += g_sig[i];
            g_gamex[i] = g; g += g_gam[i];
        }
    }
}

// ---------------- K3: chunk apply (triangular op + full per-element epilogue) ----------------
__global__ void __launch_bounds__(64) chunk_apply(const float* __restrict__ H,
                                                  const float* __restrict__ MQ,
                                                  int l, float* Zoutp, float* LDJoutp) {
    int blk = blockIdx.x;
    int b = blk / NCH, ch = blk % NCH;
    int base = b*Sn + ch*CHK;
    __shared__ float4 Hs4[CHK*Dn/4];     // 32 KB
    __shared__ float cp[Dn];
    __shared__ float zsh[CHK], csh[CHK];
    int tid = threadIdx.x;               // 64

    const float4* Hg4 = (const float4*)(H + base*Dn);
    for (int i = tid; i < CHK*Dn/4; i += 64) Hs4[i] = Hg4[i];
    zsh[tid] = g_Z[base + tid];
    csh[tid] = g_c[l*BS + base + tid];
    cp[tid*2]   = g_Cex[blk*Dn + tid*2];
    cp[tid*2+1] = g_Cex[blk*Dn + tid*2 + 1];
    __syncthreads();

    int s = tid;
    int row = base + s;
    float4 hg[32];
    const float4* hgrow = (const float4*)(g_HG + l*BS*Dn + row*Dn);
    #pragma unroll
    for (int q = 0; q < 32; q++) hg[q] = hgrow[q];

    float a_s  = g_a[l*BS + row];
    float beta = g_beta[l];

    // cross-chunk term
    float c0 = 0.f, c1 = 0.f, c2 = 0.f, c3 = 0.f;
    const float4* cp4 = (const float4*)cp;
    #pragma unroll
    for (int q = 0; q < 32; q++) {
        float4 p = cp4[q];
        c0 += hg[q].x*p.x; c1 += hg[q].y*p.y; c2 += hg[q].z*p.z; c3 += hg[q].w*p.w;
    }
    float cross = (c0 + c1) + (c2 + c3);
    float sigp = g_sigex[blk], gamp = g_gamex[blk];
    float acc_cross = SCALEF * (cross + a_s*sigp + gamp + beta*sigp);

    // intra-chunk strict-lower + diagonal score
    float intra = 0.f, selfsc = 0.f;
    int tmax = ((s >> 5) + 1) << 5;      // warp-uniform bound
    for (int t = 0; t < tmax; t++) {
        const float4* ht = Hs4 + t*32;
        float d0 = 0.f, d1 = 0.f, d2 = 0.f, d3 = 0.f;
        #pragma unroll
        for (int q = 0; q < 32; q++) {
            float4 h = ht[q];
            d0 += hg[q].x*h.x; d1 += hg[q].y*h.y; d2 += hg[q].z*h.z; d3 += hg[q].w*h.w;
        }
        float sc = SCALEF * (((d0 + d1) + (d2 + d3)) + a_s + csh[t] + beta);
        if (t < s)       intra += sc * zsh[t];
        else if (t == s) selfsc = sc;
    }

    // diag = softplus(score_ss) + 1e-3
    float sp   = fmaxf(selfsc, 0.f) + log1pf(expf(-fabsf(selfsc)));
    float diag = sp + 1e-3f;
    float y = acc_cross + intra + diag * zsh[s];

    // ---- epilogue: logdet, mask, affine, shiesh ----
    float mq = MQ[row];
    float ldj = g_LDJ[row] + logf(diag) * mq;
    float th = g_theta[l*BS + row], ph = g_phi[l*BS + row];
    float z = y * mq;
    z = z * th + ph;
    ldj += th * mq;

    const float E = 2.718281828459045f;
    float zo, sl;
    if (fabsf(z) > 5.0f) {
        zo = z + (z > 0.f ? 1.f : -1.f);
        sl = 0.f;
    } else {
        float sh = sinhf(z);
        zo = asinhf(E * sh);
        float t1 = 1.f + E * sh;
        sl = logf(E * coshf(z)) - logf(t1 * t1);
    }
    ldj += sl * mq;

    float* zo_p  = Zoutp   ? Zoutp   : g_Z;
    float* ldj_p = LDJoutp ? LDJoutp : g_LDJ;
    zo_p[row]  = zo;
    ldj_p[row] = ldj;
}

// ---------------- launch ----------------
extern "C" void kernel_launch(void* const* d_in, const int* in_sizes, int n_in,
                              void* d_out, int out_size) {
    (void)in_sizes; (void)n_in; (void)out_size;
    const float* H   = (const float*)d_in[0];
    const float* Y   = (const float*)d_in[1];
    const float* MQ  = (const float*)d_in[2];
    const float* Wq  = (const float*)d_in[3];
    const float* bq  = (const float*)d_in[4];
    const float* Wk  = (const float*)d_in[5];
    const float* bk  = (const float*)d_in[6];
    const float* tW1 = (const float*)d_in[7];
    const float* tb1 = (const float*)d_in[8];
    const float* tW2 = (const float*)d_in[9];
    const float* tb2 = (const float*)d_in[10];
    const float* pW1 = (const float*)d_in[11];
    const float* pb1 = (const float*)d_in[12];
    const float* pW2 = (const float*)d_in[13];
    const float* pb2 = (const float*)d_in[14];
    const float* wi  = (const float*)d_in[15];
    const float* bi  = (const float*)d_in[16];
    float* out = (float*)d_out;

    prep_G<<<dim3(Ln, Dn), Dn>>>(Wq, Wk, bq, bk);
    prep_rows<<<BS/8, 256>>>(H, Y, MQ, wi, bi);
    gemm_proj<<<dim3(BS/64, 9), 256>>>(H, tW1, tb1, tW2, tb2, pW1, pb1, pW2, pb2);

    for (int l = 0; l < Ln; l++) {
        chunk_sums<<<Bn*NCH, 128>>>(H, l);
        chunk_prefix<<<Bn, 128>>>();
        if (l < Ln - 1) {
            chunk_apply<<<Bn*NCH, 64>>>(H, MQ, l, nullptr, nullptr);
        } else {
            chunk_apply<<<Bn*NCH, 64>>>(H, MQ, l, out, out + BS);
        }
    }
}

// round 2
// speedup vs baseline: 1.0475x; 1.0475x over previous
#include <cuda_runtime.h>
#include <math.h>

#define Bn 8
#define Sn 2048
#define Dn 128
#define Ln 3
#define BS (Bn*Sn)          // 16384 rows
#define CHK 64
#define NCH (Sn/CHK)        // 32
#define NCHUNK (Bn*NCH)     // 256
#define SCALEF 0.08838834764831845f
#define RSTRIDE 33          // padded smem row stride in float4 (33*16=528B)

// ---------------- static device scratch ----------------
__device__ float g_G[Ln*Dn*Dn];
__device__ float g_u[Ln*Dn];
__device__ float g_v[Ln*Dn];
__device__ float g_beta[Ln];
__device__ float g_HG[Ln*BS*Dn];
__device__ float g_theta[Ln*BS];
__device__ float g_phi[Ln*BS];
__device__ float g_a[Ln*BS];
__device__ float g_c[Ln*BS];
__device__ float g_Z[BS];
__device__ float g_LDJ[BS];
__device__ float g_U[NCHUNK*Dn];
__device__ float g_Cex[NCHUNK*Dn];
__device__ float g_sig[NCHUNK];
__device__ float g_gam[NCHUNK];
__device__ float g_sigex[NCHUNK];
__device__ float g_gamex[NCHUNK];

// ---------------- P0: G = Wq Wk^T, u, v, beta ----------------
__global__ void prep_G(const float* __restrict__ Wq, const float* __restrict__ Wk,
                       const float* __restrict__ bq, const float* __restrict__ bk) {
    int l = blockIdx.x;
    int drow = blockIdx.y;
    int e = threadIdx.x;            // 128 threads
    __shared__ float wq[Dn];
    wq[e] = Wq[l*Dn*Dn + drow*Dn + e];
    __syncthreads();
    const float* wkrow = Wk + l*Dn*Dn + e*Dn;
    float acc = 0.f;
    #pragma unroll 8
    for (int j = 0; j < Dn; j++) acc += wq[j] * wkrow[j];
    g_G[l*Dn*Dn + drow*Dn + e] = acc;
    if (e == 0) {
        float s = 0.f;
        const float* bkl = bk + l*Dn;
        for (int j = 0; j < Dn; j++) s += wq[j] * bkl[j];
        g_u[l*Dn + drow] = s;
    }
    if (drow == 0) {
        float s = 0.f;
        const float* bql = bq + l*Dn;
        for (int j = 0; j < Dn; j++) s += wkrow[j] * bql[j];
        g_v[l*Dn + e] = s;
        if (e == 0) {
            float sb = 0.f;
            for (int j = 0; j < Dn; j++) sb += bql[j] * bk[l*Dn + j];
            g_beta[l] = sb;
        }
    }
}

// ---------------- P1: fused per-row MVs + Z/LDJ init + layer-0 chunk sums ----------------
__global__ void __launch_bounds__(256) prep_chunk(
        const float* __restrict__ H, const float* __restrict__ Y,
        const float* __restrict__ MQ, const float* __restrict__ wi,
        const float* __restrict__ bi) {
    __shared__ __align__(16) float4 Hs4[CHK*RSTRIDE];
    __shared__ __align__(16) float sw[7*Dn];
    __shared__ float zsh[CHK], csh0[CHK];
    int blk = blockIdx.x;            // 256 chunks
    int base = blk * CHK;
    int tid = threadIdx.x;

    for (int i = tid; i < 7*Dn; i += 256)
        sw[i] = (i < Dn) ? wi[i] : (i < 4*Dn ? g_u[i-Dn] : g_v[i-4*Dn]);
    const float4* Hg4 = (const float4*)(H + (size_t)base*Dn);
    for (int i = tid; i < CHK*32; i += 256)
        Hs4[(i>>5)*RSTRIDE + (i&31)] = Hg4[i];
    __syncthreads();

    int r = tid >> 2, p = tid & 3;
    const float4* hrow = Hs4 + r*RSTRIDE + p;
    const float4* swp = ((const float4*)sw) + p;
    float acc[7];
    #pragma unroll
    for (int k = 0; k < 7; k++) acc[k] = 0.f;
    #pragma unroll
    for (int q = 0; q < 8; q++) {
        float4 h = hrow[q*4];
        #pragma unroll
        for (int k = 0; k < 7; k++) {
            float4 w = swp[k*32 + q*4];
            acc[k] += h.x*w.x + h.y*w.y + h.z*w.z + h.w*w.w;
        }
    }
    #pragma unroll
    for (int k = 0; k < 7; k++) {
        acc[k] += __shfl_xor_sync(0xffffffffu, acc[k], 1);
        acc[k] += __shfl_xor_sync(0xffffffffu, acc[k], 2);
    }
    int row = base + r;
    if (p == 0) {
        float el0 = acc[0] + bi[0];
        float y = Y[row], mq = MQ[row];
        float z = (y*mq - el0) * mq;
        g_Z[row] = z; zsh[r] = z;
        g_LDJ[row] = 1.0f;
        #pragma unroll
        for (int l = 0; l < Ln; l++) {
            g_a[l*BS + row] = acc[1+l];
            g_c[l*BS + row] = acc[4+l];
        }
        csh0[r] = acc[4];
    }
    __syncthreads();
    const float* Hsf = (const float*)Hs4;
    if (tid < Dn) {
        float a = 0.f;
        #pragma unroll 8
        for (int t = 0; t < CHK; t++) a += Hsf[t*(RSTRIDE*4) + tid] * zsh[t];
        g_U[blk*Dn + tid] = a;
    }
    if (tid == 255) {
        float s = 0.f, g = 0.f;
        for (int t = 0; t < CHK; t++) { s += zsh[t]; g += csh0[t]*zsh[t]; }
        g_sig[blk] = s; g_gam[blk] = g;
    }
}

// ---------------- P2: 128x128-tile projection GEMM (9 GEMMs via grid.y) ----------------
__global__ void __launch_bounds__(256) gemm_proj(
    const float* __restrict__ H,
    const float* __restrict__ tW1, const float* __restrict__ tb1,
    const float* __restrict__ tW2, const float* __restrict__ tb2,
    const float* __restrict__ pW1, const float* __restrict__ pb1,
    const float* __restrict__ pW2, const float* __restrict__ pb2) {

    __shared__ __align__(16) float As[16*132];
    __shared__ __align__(16) float Bs[16*128];

    int w = blockIdx.y;
    int l = w / 3, kind = w - l*3;
    const float* Wmat;
    const float* bia1 = nullptr;
    if (kind == 0)      { Wmat = g_G + l*Dn*Dn; }
    else if (kind == 1) { Wmat = tW1 + l*Dn*Dn; bia1 = tb1 + l*Dn; }
    else                { Wmat = pW1 + l*Dn*Dn; bia1 = pb1 + l*Dn; }

    int m0 = blockIdx.x * 128;
    int tid = threadIdx.x;
    int tx = tid & 15, ty = tid >> 4;      // tx: n-groups, ty: m-groups of 8
    float acc[8][8];
    #pragma unroll
    for (int i = 0; i < 8; i++)
        #pragma unroll
        for (int j = 0; j < 8; j++) acc[i][j] = 0.f;

    for (int k0 = 0; k0 < Dn; k0 += 16) {
        #pragma unroll
        for (int it = 0; it < 2; it++) {
            int idx = tid + it*256;
            int rr = idx >> 2, kq = idx & 3;
            float4 av = *(const float4*)(H + (size_t)(m0+rr)*Dn + k0 + kq*4);
            As[(kq*4+0)*132 + rr] = av.x;
            As[(kq*4+1)*132 + rr] = av.y;
            As[(kq*4+2)*132 + rr] = av.z;
            As[(kq*4+3)*132 + rr] = av.w;
        }
        #pragma unroll
        for (int it = 0; it < 2; it++) {
            int idx = tid + it*256;
            int kk = idx >> 5, nn = (idx & 31)*4;
            *(float4*)&Bs[kk*128 + nn] = *(const float4*)(Wmat + (k0+kk)*Dn + nn);
        }
        __syncthreads();
        #pragma unroll
        for (int k = 0; k < 16; k++) {
            float4 a0 = *(float4*)&As[k*132 + ty*8];
            float4 a1 = *(float4*)&As[k*132 + ty*8 + 4];
            float4 b0 = *(float4*)&Bs[k*128 + tx*4];
            float4 b1 = *(float4*)&Bs[k*128 + 64 + tx*4];
            float am[8] = {a0.x,a0.y,a0.z,a0.w,a1.x,a1.y,a1.z,a1.w};
            float bn[8] = {b0.x,b0.y,b0.z,b0.w,b1.x,b1.y,b1.z,b1.w};
            #pragma unroll
            for (int i = 0; i < 8; i++)
                #pragma unroll
                for (int j = 0; j < 8; j++)
                    acc[i][j] += am[i]*bn[j];
        }
        __syncthreads();
    }

    if (kind == 0) {
        float* outp = g_HG + (size_t)l*BS*Dn;
        #pragma unroll
        for (int i = 0; i < 8; i++) {
            int m = m0 + ty*8 + i;
            *(float4*)(outp + (size_t)m*Dn + tx*4) =
                make_float4(acc[i][0], acc[i][1], acc[i][2], acc[i][3]);
            *(float4*)(outp + (size_t)m*Dn + 64 + tx*4) =
                make_float4(acc[i][4], acc[i][5], acc[i][6], acc[i][7]);
        }
    } else {
        const float* W2 = (kind == 1 ? tW2 : pW2) + l*Dn;
        float bias2 = (kind == 1 ? tb2 : pb2)[l];
        float4 bb0 = *(const float4*)(bia1 + tx*4);
        float4 bb1 = *(const float4*)(bia1 + 64 + tx*4);
        float4 w20 = *(const float4*)(W2 + tx*4);
        float4 w21 = *(const float4*)(W2 + 64 + tx*4);
        float* outv = (kind == 1 ? g_theta : g_phi) + l*BS;
        #pragma unroll
        for (int i = 0; i < 8; i++) {
            float part =
                fmaxf(acc[i][0]+bb0.x,0.f)*w20.x + fmaxf(acc[i][1]+bb0.y,0.f)*w20.y +
                fmaxf(acc[i][2]+bb0.z,0.f)*w20.z + fmaxf(acc[i][3]+bb0.w,0.f)*w20.w +
                fmaxf(acc[i][4]+bb1.x,0.f)*w21.x + fmaxf(acc[i][5]+bb1.y,0.f)*w21.y +
                fmaxf(acc[i][6]+bb1.z,0.f)*w21.z + fmaxf(acc[i][7]+bb1.w,0.f)*w21.w;
            part += __shfl_down_sync(0xffffffffu, part, 8, 16);
            part += __shfl_down_sync(0xffffffffu, part, 4, 16);
            part += __shfl_down_sync(0xffffffffu, part, 2, 16);
            part += __shfl_down_sync(0xffffffffu, part, 1, 16);
            if (tx == 0) {
                float v = part + bias2;
                outv[m0 + ty*8 + i] = (kind == 1) ? expf(tanhf(v)) : v;
            }
        }
    }
}

// ---------------- K2: exclusive chunk prefix ----------------
__global__ void chunk_prefix() {
    int b = blockIdx.x;      // Bn
    int tid = threadIdx.x;   // 128
    float acc = 0.f;
    for (int ch = 0; ch < NCH; ch++) {
        int idx = (b*NCH + ch)*Dn + tid;
        g_Cex[idx] = acc;
        acc += g_U[idx];
    }
    if (tid == 0) {
        float s = 0.f, g = 0.f;
        for (int ch = 0; ch < NCH; ch++) {
            int i = b*NCH + ch;
            g_sigex[i] = s; s += g_sig[i];
            g_gamex[i] = g; g += g_gam[i];
        }
    }
}

// ---------------- K3: chunk apply (4 threads/row) + fused next-layer sums ----------------
__global__ void __launch_bounds__(256) chunk_apply(
        const float* __restrict__ H, const float* __restrict__ MQ,
        int l, int fuse_next, float* Zoutp, float* LDJoutp) {
    __shared__ __align__(16) float4 Hs4[CHK*RSTRIDE];
    __shared__ __align__(16) float cp[Dn];
    __shared__ float zsh[CHK], csh[CHK], cshn[CHK], zo_sh[CHK];
    int blk = blockIdx.x;
    int base = blk * CHK;
    int tid = threadIdx.x;

    const float4* Hg4 = (const float4*)(H + (size_t)base*Dn);
    for (int i = tid; i < CHK*32; i += 256)
        Hs4[(i>>5)*RSTRIDE + (i&31)] = Hg4[i];
    if (tid < CHK) {
        zsh[tid] = g_Z[base + tid];
        csh[tid] = g_c[l*BS + base + tid];
        cshn[tid] = fuse_next ? g_c[(l+1)*BS + base + tid] : 0.f;
    }
    if (tid >= 128) cp[tid-128] = g_Cex[blk*Dn + tid-128];
    __syncthreads();

    int s = tid >> 2, p = tid & 3;
    int row = base + s;
    // interleaved D-split: thread p owns float4 indices {p, p+4, ..., p+28}
    float4 hg[8];
    const float4* hgrow = (const float4*)(g_HG + (size_t)l*BS*Dn + (size_t)row*Dn) + p;
    #pragma unroll
    for (int q = 0; q < 8; q++) hg[q] = hgrow[q*4];

    float a_s  = g_a[l*BS + row];
    float beta = g_beta[l];

    // cross-chunk partial
    float cr = 0.f;
    const float4* cp4 = ((const float4*)cp) + p;
    #pragma unroll
    for (int q = 0; q < 8; q++) {
        float4 c4 = cp4[q*4];
        cr += hg[q].x*c4.x + hg[q].y*c4.y + hg[q].z*c4.z + hg[q].w*c4.w;
    }

    // intra-chunk strict-lower + diag
    float ip = 0.f, szl = 0.f, scz = 0.f, dself = 0.f;
    int tmax = (s | 7) + 1;      // warp-uniform (8 rows per warp)
    for (int t = 0; t < tmax; t++) {
        const float4* ht = Hs4 + t*RSTRIDE + p;
        float d = 0.f;
        #pragma unroll
        for (int q = 0; q < 8; q++) {
            float4 h = ht[q*4];
            d += hg[q].x*h.x + hg[q].y*h.y + hg[q].z*h.z + hg[q].w*h.w;
        }
        float zt = zsh[t];
        if (t < s) {
            ip += d * zt;
            if (p == 0) { szl += zt; scz += csh[t]*zt; }
        } else if (t == s) dself = d;
    }
    ip    += __shfl_xor_sync(0xffffffffu, ip, 1);
    ip    += __shfl_xor_sync(0xffffffffu, ip, 2);
    dself += __shfl_xor_sync(0xffffffffu, dself, 1);
    dself += __shfl_xor_sync(0xffffffffu, dself, 2);
    cr    += __shfl_xor_sync(0xffffffffu, cr, 1);
    cr    += __shfl_xor_sync(0xffffffffu, cr, 2);

    if (p == 0) {
        float sigp = g_sigex[blk], gamp = g_gamex[blk];
        float selfsc = SCALEF * (dself + a_s + csh[s] + beta);
        float sp   = fmaxf(selfsc, 0.f) + log1pf(expf(-fabsf(selfsc)));
        float diag = sp + 1e-3f;
        float y = SCALEF*(cr + a_s*sigp + gamp + beta*sigp)
                + SCALEF*(ip + a_s*szl + scz + beta*szl)
                + diag * zsh[s];

        float mq = MQ[row];
        float ldj = g_LDJ[row] + logf(diag) * mq;
        float th = g_theta[l*BS + row], ph = g_phi[l*BS + row];
        float z = y * mq * th + ph;
        ldj += th * mq;

        const float E = 2.718281828459045f;
        float zo, sl;
        if (fabsf(z) > 5.0f) {
            zo = z + (z > 0.f ? 1.f : -1.f);
            sl = 0.f;
        } else {
            float sh = sinhf(z);
            zo = asinhf(E * sh);
            float t1 = 1.f + E * sh;
            sl = logf(E * coshf(z)) - logf(t1 * t1);
        }
        ldj += sl * mq;

        zo_sh[s] = zo;
        if (Zoutp) { Zoutp[row] = zo; LDJoutp[row] = ldj; }
        else       { g_Z[row] = zo;   g_LDJ[row] = ldj; }
    }

    if (fuse_next) {
        __syncthreads();
        const float* Hsf = (const float*)Hs4;
        if (tid < Dn) {
            float a = 0.f;
            #pragma unroll 8
            for (int t = 0; t < CHK; t++) a += Hsf[t*(RSTRIDE*4) + tid] * zo_sh[t];
            g_U[blk*Dn + tid] = a;
        }
        if (tid == 255) {
            float ssum = 0.f, gsum = 0.f;
            for (int t = 0; t < CHK; t++) { ssum += zo_sh[t]; gsum += cshn[t]*zo_sh[t]; }
            g_sig[blk] = ssum; g_gam[blk] = gsum;
        }
    }
}

// ---------------- launch ----------------
extern "C" void kernel_launch(void* const* d_in, const int* in_sizes, int n_in,
                              void* d_out, int out_size) {
    (void)in_sizes; (void)n_in; (void)out_size;
    const float* H   = (const float*)d_in[0];
    const float* Y   = (const float*)d_in[1];
    const float* MQ  = (const float*)d_in[2];
    const float* Wq  = (const float*)d_in[3];
    const float* bq  = (const float*)d_in[4];
    const float* Wk  = (const float*)d_in[5];
    const float* bk  = (const float*)d_in[6];
    const float* tW1 = (const float*)d_in[7];
    const float* tb1 = (const float*)d_in[8];
    const float* tW2 = (const float*)d_in[9];
    const float* tb2 = (const float*)d_in[10];
    const float* pW1 = (const float*)d_in[11];
    const float* pb1 = (const float*)d_in[12];
    const float* pW2 = (const float*)d_in[13];
    const float* pb2 = (const float*)d_in[14];
    const float* wi  = (const float*)d_in[15];
    const float* bi  = (const float*)d_in[16];
    float* out = (float*)d_out;

    prep_G<<<dim3(Ln, Dn), Dn>>>(Wq, Wk, bq, bk);
    prep_chunk<<<NCHUNK, 256>>>(H, Y, MQ, wi, bi);
    gemm_proj<<<dim3(BS/128, 9), 256>>>(H, tW1, tb1, tW2, tb2, pW1, pb1, pW2, pb2);

    for (int l = 0; l < Ln; l++) {
        chunk_prefix<<<Bn, 128>>>();
        if (l < Ln - 1) {
            chunk_apply<<<NCHUNK, 256>>>(H, MQ, l, 1, nullptr, nullptr);
        } else {
            chunk_apply<<<NCHUNK, 256>>>(H, MQ, l, 0, out, out + BS);
        }
    }
}

// round 3
// speedup vs baseline: 1.2547x; 1.1978x over previous
#include <cuda_runtime.h>
#include <math.h>

#define Bn 8
#define Sn 2048
#define Dn 128
#define Ln 3
#define BS (Bn*Sn)          // 16384 rows
#define CHK 64
#define NCH (Sn/CHK)        // 32
#define NCHUNK (Bn*NCH)     // 256
#define SCALEF 0.08838834764831845f
#define RSTRIDE 33          // padded smem row stride in float4

// ---------------- static device scratch ----------------
__device__ float g_G[Ln*Dn*Dn];
__device__ float g_u[Ln*Dn];
__device__ float g_v[Ln*Dn];
__device__ float g_beta[Ln];
__device__ float g_HG[Ln*BS*Dn];
__device__ float g_theta[Ln*BS];
__device__ float g_phi[Ln*BS];
__device__ float g_a[Ln*BS];
__device__ float g_c[Ln*BS];
__device__ float g_Z[BS];
__device__ float g_LDJ[BS];
__device__ float g_U[NCHUNK*Dn];
__device__ float g_Cex[NCHUNK*Dn];
__device__ float g_sig[NCHUNK];
__device__ float g_gam[NCHUNK];
__device__ float g_sigex[NCHUNK];
__device__ float g_gamex[NCHUNK];

// ---------------- P0: G = Wq Wk^T, u, v, beta ----------------
__global__ void prep_G(const float* __restrict__ Wq, const float* __restrict__ Wk,
                       const float* __restrict__ bq, const float* __restrict__ bk) {
    int l = blockIdx.x;
    int drow = blockIdx.y;
    int e = threadIdx.x;            // 128 threads
    __shared__ float wq[Dn];
    wq[e] = Wq[l*Dn*Dn + drow*Dn + e];
    __syncthreads();
    const float* wkrow = Wk + l*Dn*Dn + e*Dn;
    float acc = 0.f;
    #pragma unroll 8
    for (int j = 0; j < Dn; j++) acc += wq[j] * wkrow[j];
    g_G[l*Dn*Dn + drow*Dn + e] = acc;
    if (e == 0) {
        float s = 0.f;
        const float* bkl = bk + l*Dn;
        for (int j = 0; j < Dn; j++) s += wq[j] * bkl[j];
        g_u[l*Dn + drow] = s;
    }
    if (drow == 0) {
        float s = 0.f;
        const float* bql = bq + l*Dn;
        for (int j = 0; j < Dn; j++) s += wkrow[j] * bql[j];
        g_v[l*Dn + e] = s;
        if (e == 0) {
            float sb = 0.f;
            for (int j = 0; j < Dn; j++) sb += bql[j] * bk[l*Dn + j];
            g_beta[l] = sb;
        }
    }
}

// ---------------- P1: fused per-row MVs + Z/LDJ init + layer-0 chunk sums ----------------
__global__ void __launch_bounds__(256) prep_chunk(
        const float* __restrict__ H, const float* __restrict__ Y,
        const float* __restrict__ MQ, const float* __restrict__ wi,
        const float* __restrict__ bi) {
    __shared__ __align__(16) float4 Hs4[CHK*RSTRIDE];
    __shared__ __align__(16) float sw[7*Dn];
    __shared__ float zsh[CHK], csh0[CHK];
    int blk = blockIdx.x;            // 256 chunks
    int base = blk * CHK;
    int tid = threadIdx.x;

    for (int i = tid; i < 7*Dn; i += 256)
        sw[i] = (i < Dn) ? wi[i] : (i < 4*Dn ? g_u[i-Dn] : g_v[i-4*Dn]);
    const float4* Hg4 = (const float4*)(H + (size_t)base*Dn);
    for (int i = tid; i < CHK*32; i += 256)
        Hs4[(i>>5)*RSTRIDE + (i&31)] = Hg4[i];
    __syncthreads();

    int r = tid >> 2, p = tid & 3;
    const float4* hrow = Hs4 + r*RSTRIDE + p;
    const float4* swp = ((const float4*)sw) + p;
    float acc[7];
    #pragma unroll
    for (int k = 0; k < 7; k++) acc[k] = 0.f;
    #pragma unroll
    for (int q = 0; q < 8; q++) {
        float4 h = hrow[q*4];
        #pragma unroll
        for (int k = 0; k < 7; k++) {
            float4 w = swp[k*32 + q*4];
            acc[k] += h.x*w.x + h.y*w.y + h.z*w.z + h.w*w.w;
        }
    }
    #pragma unroll
    for (int k = 0; k < 7; k++) {
        acc[k] += __shfl_xor_sync(0xffffffffu, acc[k], 1);
        acc[k] += __shfl_xor_sync(0xffffffffu, acc[k], 2);
    }
    int row = base + r;
    if (p == 0) {
        float el0 = acc[0] + bi[0];
        float y = Y[row], mq = MQ[row];
        float z = (y*mq - el0) * mq;
        g_Z[row] = z; zsh[r] = z;
        g_LDJ[row] = 1.0f;
        #pragma unroll
        for (int l = 0; l < Ln; l++) {
            g_a[l*BS + row] = acc[1+l];
            g_c[l*BS + row] = acc[4+l];
        }
        csh0[r] = acc[4];
    }
    __syncthreads();
    const float* Hsf = (const float*)Hs4;
    if (tid < Dn) {
        float a = 0.f;
        #pragma unroll 8
        for (int t = 0; t < CHK; t++) a += Hsf[t*(RSTRIDE*4) + tid] * zsh[t];
        g_U[blk*Dn + tid] = a;
    }
    if (tid == 255) {
        float s = 0.f, g = 0.f;
        for (int t = 0; t < CHK; t++) { s += zsh[t]; g += csh0[t]*zsh[t]; }
        g_sig[blk] = s; g_gam[blk] = g;
    }
}

// ---------------- P2: 128x128-tile projection GEMM (9 GEMMs via grid.y) ----------------
__global__ void __launch_bounds__(256) gemm_proj(
    const float* __restrict__ H,
    const float* __restrict__ tW1, const float* __restrict__ tb1,
    const float* __restrict__ tW2, const float* __restrict__ tb2,
    const float* __restrict__ pW1, const float* __restrict__ pb1,
    const float* __restrict__ pW2, const float* __restrict__ pb2) {

    __shared__ __align__(16) float As[16*132];
    __shared__ __align__(16) float Bs[16*128];

    int w = blockIdx.y;
    int l = w / 3, kind = w - l*3;
    const float* Wmat;
    const float* bia1 = nullptr;
    if (kind == 0)      { Wmat = g_G + l*Dn*Dn; }
    else if (kind == 1) { Wmat = tW1 + l*Dn*Dn; bia1 = tb1 + l*Dn; }
    else                { Wmat = pW1 + l*Dn*Dn; bia1 = pb1 + l*Dn; }

    int m0 = blockIdx.x * 128;
    int tid = threadIdx.x;
    int tx = tid & 15, ty = tid >> 4;
    float acc[8][8];
    #pragma unroll
    for (int i = 0; i < 8; i++)
        #pragma unroll
        for (int j = 0; j < 8; j++) acc[i][j] = 0.f;

    for (int k0 = 0; k0 < Dn; k0 += 16) {
        #pragma unroll
        for (int it = 0; it < 2; it++) {
            int idx = tid + it*256;
            int rr = idx >> 2, kq = idx & 3;
            float4 av = *(const float4*)(H + (size_t)(m0+rr)*Dn + k0 + kq*4);
            As[(kq*4+0)*132 + rr] = av.x;
            As[(kq*4+1)*132 + rr] = av.y;
            As[(kq*4+2)*132 + rr] = av.z;
            As[(kq*4+3)*132 + rr] = av.w;
        }
        #pragma unroll
        for (int it = 0; it < 2; it++) {
            int idx = tid + it*256;
            int kk = idx >> 5, nn = (idx & 31)*4;
            *(float4*)&Bs[kk*128 + nn] = *(const float4*)(Wmat + (k0+kk)*Dn + nn);
        }
        __syncthreads();
        #pragma unroll
        for (int k = 0; k < 16; k++) {
            float4 a0 = *(float4*)&As[k*132 + ty*8];
            float4 a1 = *(float4*)&As[k*132 + ty*8 + 4];
            float4 b0 = *(float4*)&Bs[k*128 + tx*4];
            float4 b1 = *(float4*)&Bs[k*128 + 64 + tx*4];
            float am[8] = {a0.x,a0.y,a0.z,a0.w,a1.x,a1.y,a1.z,a1.w};
            float bn[8] = {b0.x,b0.y,b0.z,b0.w,b1.x,b1.y,b1.z,b1.w};
            #pragma unroll
            for (int i = 0; i < 8; i++)
                #pragma unroll
                for (int j = 0; j < 8; j++)
                    acc[i][j] += am[i]*bn[j];
        }
        __syncthreads();
    }

    if (kind == 0) {
        float* outp = g_HG + (size_t)l*BS*Dn;
        #pragma unroll
        for (int i = 0; i < 8; i++) {
            int m = m0 + ty*8 + i;
            *(float4*)(outp + (size_t)m*Dn + tx*4) =
                make_float4(acc[i][0], acc[i][1], acc[i][2], acc[i][3]);
            *(float4*)(outp + (size_t)m*Dn + 64 + tx*4) =
                make_float4(acc[i][4], acc[i][5], acc[i][6], acc[i][7]);
        }
    } else {
        const float* W2 = (kind == 1 ? tW2 : pW2) + l*Dn;
        float bias2 = (kind == 1 ? tb2 : pb2)[l];
        float4 bb0 = *(const float4*)(bia1 + tx*4);
        float4 bb1 = *(const float4*)(bia1 + 64 + tx*4);
        float4 w20 = *(const float4*)(W2 + tx*4);
        float4 w21 = *(const float4*)(W2 + 64 + tx*4);
        float* outv = (kind == 1 ? g_theta : g_phi) + l*BS;
        #pragma unroll
        for (int i = 0; i < 8; i++) {
            float part =
                fmaxf(acc[i][0]+bb0.x,0.f)*w20.x + fmaxf(acc[i][1]+bb0.y,0.f)*w20.y +
                fmaxf(acc[i][2]+bb0.z,0.f)*w20.z + fmaxf(acc[i][3]+bb0.w,0.f)*w20.w +
                fmaxf(acc[i][4]+bb1.x,0.f)*w21.x + fmaxf(acc[i][5]+bb1.y,0.f)*w21.y +
                fmaxf(acc[i][6]+bb1.z,0.f)*w21.z + fmaxf(acc[i][7]+bb1.w,0.f)*w21.w;
            part += __shfl_down_sync(0xffffffffu, part, 8, 16);
            part += __shfl_down_sync(0xffffffffu, part, 4, 16);
            part += __shfl_down_sync(0xffffffffu, part, 2, 16);
            part += __shfl_down_sync(0xffffffffu, part, 1, 16);
            if (tx == 0) {
                float v = part + bias2;
                outv[m0 + ty*8 + i] = (kind == 1) ? expf(tanhf(v)) : v;
            }
        }
    }
}

// ---------------- K2: exclusive chunk prefix (MLP-32, register-resident) ----------------
__global__ void __launch_bounds__(128) chunk_prefix() {
    int b = blockIdx.x;      // Bn
    int tid = threadIdx.x;   // 128
    float u[NCH];
    #pragma unroll
    for (int ch = 0; ch < NCH; ch++)
        u[ch] = g_U[(b*NCH + ch)*Dn + tid];          // 32 independent loads
    float acc = 0.f;
    #pragma unroll
    for (int ch = 0; ch < NCH; ch++) {
        g_Cex[(b*NCH + ch)*Dn + tid] = acc;
        acc += u[ch];
    }
    if (tid < NCH) {
        float s = g_sig[b*NCH + tid];
        float g = g_gam[b*NCH + tid];
        float ss = s, gg = g;
        #pragma unroll
        for (int off = 1; off < 32; off <<= 1) {
            float t1 = __shfl_up_sync(0xffffffffu, ss, off);
            float t2 = __shfl_up_sync(0xffffffffu, gg, off);
            if (tid >= off) { ss += t1; gg += t2; }
        }
        g_sigex[b*NCH + tid] = ss - s;
        g_gamex[b*NCH + tid] = gg - g;
    }
}

// ---------------- K3: chunk apply, 2 rows/thread (shared ht reads) ----------------
__global__ void __launch_bounds__(128) chunk_apply(
        const float* __restrict__ H, const float* __restrict__ MQ,
        int l, int fuse_next, float* Zoutp, float* LDJoutp) {
    __shared__ __align__(16) float4 Hs4[CHK*RSTRIDE];
    __shared__ __align__(16) float cp[Dn];
    __shared__ float zsh[CHK], csh[CHK], cshn[CHK], zo_sh[CHK];
    int blk = blockIdx.x;
    int base = blk * CHK;
    int tid = threadIdx.x;               // 128

    const float4* Hg4 = (const float4*)(H + (size_t)base*Dn);
    for (int i = tid; i < CHK*32; i += 128)
        Hs4[(i>>5)*RSTRIDE + (i&31)] = Hg4[i];
    if (tid < CHK) {
        zsh[tid] = g_Z[base + tid];
        csh[tid] = g_c[l*BS + base + tid];
        cshn[tid] = fuse_next ? g_c[(l+1)*BS + base + tid] : 0.f;
    }
    cp[tid] = g_Cex[blk*Dn + tid];
    __syncthreads();

    int pr = tid >> 2, p = tid & 3;      // pr: row pair 0..31
    int r0 = 2*pr, r1 = 2*pr + 1;
    int row0 = base + r0, row1 = base + r1;

    float4 hg0[8], hg1[8];
    const float4* hgr0 = (const float4*)(g_HG + (size_t)l*BS*Dn + (size_t)row0*Dn) + p;
    const float4* hgr1 = (const float4*)(g_HG + (size_t)l*BS*Dn + (size_t)row1*Dn) + p;
    #pragma unroll
    for (int q = 0; q < 8; q++) { hg0[q] = hgr0[q*4]; hg1[q] = hgr1[q*4]; }

    float a0 = g_a[l*BS + row0], a1 = g_a[l*BS + row1];
    float beta = g_beta[l];

    // cross-chunk partials
    float cr0 = 0.f, cr1 = 0.f;
    const float4* cp4 = ((const float4*)cp) + p;
    #pragma unroll
    for (int q = 0; q < 8; q++) {
        float4 c4 = cp4[q*4];
        cr0 += hg0[q].x*c4.x + hg0[q].y*c4.y + hg0[q].z*c4.z + hg0[q].w*c4.w;
        cr1 += hg1[q].x*c4.x + hg1[q].y*c4.y + hg1[q].z*c4.z + hg1[q].w*c4.w;
    }

    // intra-chunk strict-lower + diagonal, two rows sharing ht loads
    float ip0 = 0.f, ip1 = 0.f, ds0 = 0.f, ds1 = 0.f;
    float szl0 = 0.f, scz0 = 0.f, szl1 = 0.f, scz1 = 0.f;
    int tmax = (r1 | 15) + 1;            // warp-uniform (8 pairs = 16 rows / warp)
    for (int t = 0; t < tmax; t++) {
        const float4* ht = Hs4 + t*RSTRIDE + p;
        float d0 = 0.f, d1 = 0.f;
        #pragma unroll
        for (int q = 0; q < 8; q++) {
            float4 h = ht[q*4];
            d0 += hg0[q].x*h.x + hg0[q].y*h.y + hg0[q].z*h.z + hg0[q].w*h.w;
            d1 += hg1[q].x*h.x + hg1[q].y*h.y + hg1[q].z*h.z + hg1[q].w*h.w;
        }
        float zt = zsh[t];
        if (t < r0)       ip0 += d0 * zt;
        else if (t == r0) ds0 = d0;
        if (t < r1)       ip1 += d1 * zt;
        else if (t == r1) ds1 = d1;
        if (p == 0) {
            float ct = csh[t];
            if (t < r0) { szl0 += zt; scz0 += ct*zt; }
            if (t < r1) { szl1 += zt; scz1 += ct*zt; }
        }
    }
    #pragma unroll
    for (int off = 1; off <= 2; off <<= 1) {
        ip0 += __shfl_xor_sync(0xffffffffu, ip0, off);
        ip1 += __shfl_xor_sync(0xffffffffu, ip1, off);
        ds0 += __shfl_xor_sync(0xffffffffu, ds0, off);
        ds1 += __shfl_xor_sync(0xffffffffu, ds1, off);
        cr0 += __shfl_xor_sync(0xffffffffu, cr0, off);
        cr1 += __shfl_xor_sync(0xffffffffu, cr1, off);
    }

    if (p == 0) {
        float sigp = g_sigex[blk], gamp = g_gamex[blk];
        const float E = 2.718281828459045f;
        #pragma unroll
        for (int rr = 0; rr < 2; rr++) {
            int r    = rr ? r1   : r0;
            int row  = rr ? row1 : row0;
            float as = rr ? a1   : a0;
            float crx = rr ? cr1 : cr0;
            float ipx = rr ? ip1 : ip0;
            float dsx = rr ? ds1 : ds0;
            float szl = rr ? szl1 : szl0;
            float scz = rr ? scz1 : scz0;

            float selfsc = SCALEF * (dsx + as + csh[r] + beta);
            float sp   = fmaxf(selfsc, 0.f) + log1pf(expf(-fabsf(selfsc)));
            float diag = sp + 1e-3f;
            float y = SCALEF*(crx + as*sigp + gamp + beta*sigp)
                    + SCALEF*(ipx + as*szl + scz + beta*szl)
                    + diag * zsh[r];

            float mq = MQ[row];
            float ldj = g_LDJ[row] + logf(diag) * mq;
            float th = g_theta[l*BS + row], ph = g_phi[l*BS + row];
            float z = y * mq * th + ph;
            ldj += th * mq;

            float zo, sl;
            if (fabsf(z) > 5.0f) {
                zo = z + (z > 0.f ? 1.f : -1.f);
                sl = 0.f;
            } else {
                float sh = sinhf(z);
                zo = asinhf(E * sh);
                float t1 = 1.f + E * sh;
                sl = logf(E * coshf(z)) - logf(t1 * t1);
            }
            ldj += sl * mq;

            zo_sh[r] = zo;
            if (Zoutp) { Zoutp[row] = zo; LDJoutp[row] = ldj; }
            else       { g_Z[row] = zo;   g_LDJ[row] = ldj; }
        }
    }

    if (fuse_next) {
        __syncthreads();
        const float* Hsf = (const float*)Hs4;
        float acc2 = 0.f;
        #pragma unroll 8
        for (int t = 0; t < CHK; t++) acc2 += Hsf[t*(RSTRIDE*4) + tid] * zo_sh[t];
        g_U[blk*Dn + tid] = acc2;
        if (tid == 127) {
            float ssum = 0.f, gsum = 0.f;
            for (int t = 0; t < CHK; t++) { ssum += zo_sh[t]; gsum += cshn[t]*zo_sh[t]; }
            g_sig[blk] = ssum; g_gam[blk] = gsum;
        }
    }
}

// ---------------- launch ----------------
extern "C" void kernel_launch(void* const* d_in, const int* in_sizes, int n_in,
                              void* d_out, int out_size) {
    (void)in_sizes; (void)n_in; (void)out_size;
    const float* H   = (const float*)d_in[0];
    const float* Y   = (const float*)d_in[1];
    const float* MQ  = (const float*)d_in[2];
    const float* Wq  = (const float*)d_in[3];
    const float* bq  = (const float*)d_in[4];
    const float* Wk  = (const float*)d_in[5];
    const float* bk  = (const float*)d_in[6];
    const float* tW1 = (const float*)d_in[7];
    const float* tb1 = (const float*)d_in[8];
    const float* tW2 = (const float*)d_in[9];
    const float* tb2 = (const float*)d_in[10];
    const float* pW1 = (const float*)d_in[11];
    const float* pb1 = (const float*)d_in[12];
    const float* pW2 = (const float*)d_in[13];
    const float* pb2 = (const float*)d_in[14];
    const float* wi  = (const float*)d_in[15];
    const float* bi  = (const float*)d_in[16];
    float* out = (float*)d_out;

    prep_G<<<dim3(Ln, Dn), Dn>>>(Wq, Wk, bq, bk);
    prep_chunk<<<NCHUNK, 256>>>(H, Y, MQ, wi, bi);
    gemm_proj<<<dim3(BS/128, 9), 256>>>(H, tW1, tb1, tW2, tb2, pW1, pb1, pW2, pb2);

    for (int l = 0; l < Ln; l++) {
        chunk_prefix<<<Bn, 128>>>();
        if (l < Ln - 1) {
            chunk_apply<<<NCHUNK, 128>>>(H, MQ, l, 1, nullptr, nullptr);
        } else {
            chunk_apply<<<NCHUNK, 128>>>(H, MQ, l, 0, out, out + BS);
        }
    }
}